// round 15
// baseline (speedup 1.0000x reference)
#include <cuda_runtime.h>
#include <cuda_fp16.h>

// 2-layer GCN, N=100000, E=3200000, 25->16->2, log_softmax.
// out_l[i] = dinv[i]*(sum_{j->i} g[j] + g[i]) + b,  g = dinv * (x @ W).
// Bucketed CSR with TRANSPOSED (column-major) buckets: slot k of node i at
// d_srcb[k*NMAX + i] -> warp-coalesced index loads. Fill doubles as degree
// pass; overflow spill keeps exactness. Gathers: fp32 accumulation, fused
// epilogues; layer-1 payload fp16 (32B/node). Parity-split lanes double
// occupancy at identical sector counts. edge_index is int32 on device.

#define NMAX   100000
#define CAP    128
#define F_IN   25
#define F_HID  16
#define F_OUT  2
#define SPILLMAX 8192

struct __align__(16) H8 { __half2 h[4]; };   // 8 halfs = 16B

// ---- scratch (device globals; no allocation allowed) ----
__device__ int   d_cnt [NMAX];            // degree counters (= deg after fill)
__device__ int   d_srcb[CAP * NMAX];      // transposed buckets: [slot][node]
__device__ int   d_spill_n;
__device__ int   d_spill[2 * SPILLMAX];   // (target, source) overflow pairs
__device__ float d_dinv[NMAX];
__device__ H8    d_g1h [NMAX * 2];        // 16 halfs per node (32B)
__device__ float d_g2  [NMAX * F_OUT];

// ---- kernels ----

__global__ void k_zero(int n) {
    int i = blockIdx.x * blockDim.x + threadIdx.x;
    if (i < n) d_cnt[i] = 0;
    if (i == 0) d_spill_n = 0;
}

// Fill bucketed CSR; counters double as degree histogram.
__global__ void k_fill(const int* __restrict__ row,
                       const int* __restrict__ col, int n_edges, int n_nodes) {
    int e = blockIdx.x * blockDim.x + threadIdx.x;
    if (e >= n_edges) return;
    unsigned r = (unsigned)__ldg(&row[e]);
    unsigned t = (unsigned)__ldg(&col[e]);
    if (r >= (unsigned)n_nodes || t >= (unsigned)n_nodes) return;
    int slot = atomicAdd(&d_cnt[t], 1);
    if (slot < CAP) {
        d_srcb[slot * NMAX + t] = (int)r;
    } else {
        int s = atomicAdd(&d_spill_n, 1);
        if (s < SPILLMAX) {
            d_spill[2 * s + 0] = (int)t;
            d_spill[2 * s + 1] = (int)r;
        }
    }
}

// dinv = rsqrt(deg_in + 1);  g1 = dinv * (x @ W1), stored fp16-packed.
__global__ void k_node1(const float* __restrict__ x,
                        const float* __restrict__ W1, int n) {
    __shared__ float sW[F_IN * F_HID];
    for (int i = threadIdx.x; i < F_IN * F_HID; i += blockDim.x)
        sW[i] = W1[i];
    __syncthreads();

    int i = blockIdx.x * blockDim.x + threadIdx.x;
    if (i >= n) return;

    float xv[F_IN];
#pragma unroll
    for (int k = 0; k < F_IN; k++) xv[k] = x[i * F_IN + k];

    float dinv = rsqrtf((float)(d_cnt[i] + 1));
    d_dinv[i] = dinv;

    float s[F_HID];
#pragma unroll
    for (int f = 0; f < F_HID; f++) {
        float acc = 0.0f;
#pragma unroll
        for (int k = 0; k < F_IN; k++) acc += xv[k] * sW[k * F_HID + f];
        s[f] = dinv * acc;
    }
#pragma unroll
    for (int c = 0; c < 2; c++) {
        H8 o;
#pragma unroll
        for (int k = 0; k < 4; k++)
            o.h[k] = __floats2half2_rn(s[c * 8 + 2 * k], s[c * 8 + 2 * k + 1]);
        d_g1h[i * 2 + c] = o;
    }
}

// Gather layer 1 + epilogue-1 + layer-2 transform, fused.
// 4 lanes/node: bit0 = feature half (part), bit1 = neighbor parity (half).
// Index loads stay warp-coalesced (8 consecutive nodes per k-row = 1 sector
// per parity); payload lane pairs coalesce to one 32B sector per neighbor.
__global__ void k_gather1(const float* __restrict__ b1,
                          const float* __restrict__ W2, int n) {
    int gid = blockIdx.x * blockDim.x + threadIdx.x;
    int i = gid >> 2;
    int c = gid & 3;
    int part = c & 1;      // feature half
    int half = c >> 1;     // neighbor parity
    bool valid = (i < n);
    int ic = valid ? i : (n - 1);   // clamp: keep quad active for shfl

    int cnt = d_cnt[ic];
    int deg = min(cnt, CAP);
    float dinv = d_dinv[ic];

    float a[8];
#pragma unroll
    for (int q = 0; q < 8; q++) a[q] = 0.0f;

    int k = half;
    for (; k + 6 < deg; k += 8) {
        int j0 = __ldg(&d_srcb[(k + 0) * NMAX + ic]);
        int j1 = __ldg(&d_srcb[(k + 2) * NMAX + ic]);
        int j2 = __ldg(&d_srcb[(k + 4) * NMAX + ic]);
        int j3 = __ldg(&d_srcb[(k + 6) * NMAX + ic]);
        H8 v0 = d_g1h[j0 * 2 + part];
        H8 v1 = d_g1h[j1 * 2 + part];
        H8 v2 = d_g1h[j2 * 2 + part];
        H8 v3 = d_g1h[j3 * 2 + part];
#pragma unroll
        for (int q = 0; q < 4; q++) {
            float2 f0 = __half22float2(v0.h[q]);
            float2 f1 = __half22float2(v1.h[q]);
            float2 f2 = __half22float2(v2.h[q]);
            float2 f3 = __half22float2(v3.h[q]);
            a[2 * q]     += (f0.x + f1.x) + (f2.x + f3.x);
            a[2 * q + 1] += (f0.y + f1.y) + (f2.y + f3.y);
        }
    }
    for (; k < deg; k += 2) {
        int j = __ldg(&d_srcb[k * NMAX + ic]);
        H8 v = d_g1h[j * 2 + part];
#pragma unroll
        for (int q = 0; q < 4; q++) {
            float2 f = __half22float2(v.h[q]);
            a[2 * q] += f.x; a[2 * q + 1] += f.y;
        }
    }

    // overflow path (expected never taken): parity-0 lanes scan spill list
    if (cnt > CAP && half == 0) {
        int ns = min(d_spill_n, SPILLMAX);
        for (int s = 0; s < ns; s++) {
            if (d_spill[2 * s] == ic) {
                int j = d_spill[2 * s + 1];
                H8 v = d_g1h[j * 2 + part];
#pragma unroll
                for (int q = 0; q < 4; q++) {
                    float2 f = __half22float2(v.h[q]);
                    a[2 * q] += f.x; a[2 * q + 1] += f.y;
                }
            }
        }
    }

    // merge neighbor parities (lanes differ in bit 1)
#pragma unroll
    for (int q = 0; q < 8; q++)
        a[q] += __shfl_xor_sync(0xffffffffu, a[q], 2);

    // self term, once (all lanes now hold the parity-merged sum)
    {
        H8 v = d_g1h[ic * 2 + part];
#pragma unroll
        for (int q = 0; q < 4; q++) {
            float2 f = __half22float2(v.h[q]);
            a[2 * q] += f.x; a[2 * q + 1] += f.y;
        }
    }

    // epilogue-1: relu(dinv*a + b1), partial dot into W2
    float h0 = 0.0f, h1 = 0.0f;
#pragma unroll
    for (int f = 0; f < 8; f++) {
        int fg = part * 8 + f;
        float tt = fmaxf(dinv * a[f] + __ldg(&b1[fg]), 0.0f);
        h0 += tt * __ldg(&W2[fg * F_OUT + 0]);
        h1 += tt * __ldg(&W2[fg * F_OUT + 1]);
    }
    // merge feature halves (lanes differ in bit 0)
    h0 += __shfl_xor_sync(0xffffffffu, h0, 1);
    h1 += __shfl_xor_sync(0xffffffffu, h1, 1);

    if (valid && c == 0) {
        d_g2[i * 2 + 0] = dinv * h0;
        d_g2[i * 2 + 1] = dinv * h1;
    }
}

// Gather layer 2 + epilogue-2 + log_softmax, fused. 2 lanes/node (parity).
__global__ void k_gather2(const float* __restrict__ b2,
                          float* __restrict__ out, int n) {
    int gid = blockIdx.x * blockDim.x + threadIdx.x;
    int i = gid >> 1;
    int c = gid & 1;
    bool valid = (i < n);
    int ic = valid ? i : (n - 1);

    int cnt = d_cnt[ic];
    int deg = min(cnt, CAP);
    float dinv = d_dinv[ic];

    float2 acc = make_float2(0.0f, 0.0f);

    int k = c;
    for (; k + 6 < deg; k += 8) {
        int j0 = __ldg(&d_srcb[(k + 0) * NMAX + ic]);
        int j1 = __ldg(&d_srcb[(k + 2) * NMAX + ic]);
        int j2 = __ldg(&d_srcb[(k + 4) * NMAX + ic]);
        int j3 = __ldg(&d_srcb[(k + 6) * NMAX + ic]);
        float2 v0 = *reinterpret_cast<const float2*>(&d_g2[j0 * 2]);
        float2 v1 = *reinterpret_cast<const float2*>(&d_g2[j1 * 2]);
        float2 v2 = *reinterpret_cast<const float2*>(&d_g2[j2 * 2]);
        float2 v3 = *reinterpret_cast<const float2*>(&d_g2[j3 * 2]);
        acc.x += (v0.x + v1.x) + (v2.x + v3.x);
        acc.y += (v0.y + v1.y) + (v2.y + v3.y);
    }
    for (; k < deg; k += 2) {
        int j = __ldg(&d_srcb[k * NMAX + ic]);
        float2 v = *reinterpret_cast<const float2*>(&d_g2[j * 2]);
        acc.x += v.x; acc.y += v.y;
    }

    if (cnt > CAP && c == 0) {
        int ns = min(d_spill_n, SPILLMAX);
        for (int s = 0; s < ns; s++) {
            if (d_spill[2 * s] == ic) {
                int j = d_spill[2 * s + 1];
                float2 v = *reinterpret_cast<const float2*>(&d_g2[j * 2]);
                acc.x += v.x; acc.y += v.y;
            }
        }
    }

    // merge parities (lanes differ in bit 0)
    acc.x += __shfl_xor_sync(0xffffffffu, acc.x, 1);
    acc.y += __shfl_xor_sync(0xffffffffu, acc.y, 1);

    if (valid && c == 0) {
        float2 g = *reinterpret_cast<const float2*>(&d_g2[i * 2]);  // self
        float z0 = dinv * (acc.x + g.x) + __ldg(&b2[0]);
        float z1 = dinv * (acc.y + g.y) + __ldg(&b2[1]);
        float m = fmaxf(z0, z1);
        float lse = m + logf(expf(z0 - m) + expf(z1 - m));
        out[i * 2 + 0] = z0 - lse;
        out[i * 2 + 1] = z1 - lse;
    }
}

// ---- launch ----

extern "C" void kernel_launch(void* const* d_in, const int* in_sizes, int n_in,
                              void* d_out, int out_size) {
    const float* x  = (const float*)d_in[0];
    const int*   ei = (const int*)d_in[1];
    const float* W1 = (const float*)d_in[2];
    const float* b1 = (const float*)d_in[3];
    const float* W2 = (const float*)d_in[4];
    const float* b2 = (const float*)d_in[5];
    float*       out = (float*)d_out;

    int n_nodes = in_sizes[0] / F_IN;
    int n_edges = in_sizes[1] / 2;
    const int* row = ei;             // sources
    const int* col = ei + n_edges;   // targets

    const int B = 256;
    int gn  = (n_nodes + B - 1) / B;
    int ge  = (n_edges + B - 1) / B;
    int gn2 = (int)((2LL * n_nodes + B - 1) / B);
    int gn4 = (int)((4LL * n_nodes + B - 1) / B);

    k_zero   <<<gn, B>>>(n_nodes);
    k_fill   <<<ge, B>>>(row, col, n_edges, n_nodes);
    k_node1  <<<gn, B>>>(x, W1, n_nodes);
    k_gather1<<<gn4, B>>>(b1, W2, n_nodes);
    k_gather2<<<gn2, B>>>(b2, out, n_nodes);
}